// round 2
// baseline (speedup 1.0000x reference)
#include <cuda_runtime.h>
#include <math.h>

// Problem constants
#define BATCH 256
#define TSEQ  96
#define PRED  96
#define CIN   321
#define DM    512
#define G4    2048   // 4*DM
#define HD    (BATCH*DM)   // 131072

// ---------------- device scratch (static globals; no runtime alloc) -----------
__device__ float g_mean[BATCH*CIN];
__device__ float g_std [BATCH*CIN];
__device__ float g_istd[BATCH*CIN];
__device__ float g_Gx  [BATCH*TSEQ*G4];     // 201 MB: x_t @ Wih^T for all enc steps
__device__ float g_Wd  [G4*DM];             // Whh + Wih@Wp
__device__ float g_bd  [G4];
__device__ float g_benc[G4];
__device__ float g_h   [2*HD];              // ping-pong hidden state
__device__ float g_c   [HD];
__device__ float g_Hdec[PRED*HD];           // decoder-input hidden states

// ---------------- f32x2 packed-FMA helpers (Blackwell) ------------------------
__device__ __forceinline__ unsigned long long dup2(float x) {
    unsigned long long r;
    asm("mov.b64 %0, {%1, %2};" : "=l"(r) : "f"(x), "f"(x));
    return r;
}
__device__ __forceinline__ void fma2(unsigned long long& d, unsigned long long a, unsigned long long b) {
    asm("fma.rn.f32x2 %0, %1, %2, %0;" : "+l"(d) : "l"(a), "l"(b));
}
__device__ __forceinline__ float lo32(unsigned long long v) { return __uint_as_float((unsigned)v); }
__device__ __forceinline__ float hi32(unsigned long long v) { return __uint_as_float((unsigned)(v >> 32)); }
__device__ __forceinline__ float sigf(float x) { return 1.f / (1.f + expf(-x)); }

// ---------------- stats: mean/std over time per (b, ch) -----------------------
__global__ __launch_bounds__(256) void stats_kernel(const float* __restrict__ x) {
    int idx = blockIdx.x * 256 + threadIdx.x;          // 256*321 threads exactly
    if (idx >= BATCH * CIN) return;
    int b = idx / CIN, ch = idx % CIN;
    float s = 0.f, ss = 0.f;
    const float* p = x + (long)b * TSEQ * CIN + ch;
    #pragma unroll 4
    for (int t = 0; t < TSEQ; t++) { float v = p[t * CIN]; s += v; ss += v * v; }
    float mean = s * (1.f / TSEQ);
    float var = ss * (1.f / TSEQ) - mean * mean;
    if (var < 0.f) var = 0.f;
    float sd = sqrtf(var + 1e-5f);
    g_mean[idx] = mean; g_std[idx] = sd; g_istd[idx] = 1.f / sd;
}

// ---------------- bias fold: benc = bih+bhh ; bd = benc + Wih@bp --------------
__global__ __launch_bounds__(256) void bias_kernel(const float* __restrict__ bih,
                                                   const float* __restrict__ bhh,
                                                   const float* __restrict__ Wih,
                                                   const float* __restrict__ bp) {
    int n = blockIdx.x * 256 + threadIdx.x;
    if (n >= G4) return;
    float be = bih[n] + bhh[n];
    float s = 0.f;
    const float* w = Wih + (long)n * CIN;
    for (int j = 0; j < CIN; j++) s += w[j] * bp[j];
    g_benc[n] = be;
    g_bd[n] = be + s;
}

// ---------------- Wd = Whh + Wih @ Wp  (2048x512, K=321), plain fp32 ----------
__global__ __launch_bounds__(256) void wd_kernel(const float* __restrict__ Wih,
                                                 const float* __restrict__ Wp,
                                                 const float* __restrict__ Whh) {
    __shared__ float As[64 * 17];   // [m][j]
    __shared__ float Bs[16 * 65];   // [j][n]
    int tid = threadIdx.x;
    int n0 = blockIdx.x * 64;       // k-dim of Wd (0..511)
    int m0 = blockIdx.y * 64;       // n-dim (rows of Wih, 0..2047)
    int tr = tid >> 4, tc = tid & 15;
    float acc[4][4] = {};
    for (int j0 = 0; j0 < CIN; j0 += 16) {
        #pragma unroll
        for (int i = 0; i < 4; i++) {
            int l = tid + 256 * i;
            int mr = l >> 4, jj = l & 15;
            int j = j0 + jj;
            As[mr * 17 + jj] = (j < CIN) ? Wih[(long)(m0 + mr) * CIN + j] : 0.f;
        }
        #pragma unroll
        for (int i = 0; i < 4; i++) {
            int l = tid + 256 * i;
            int jj = l >> 6, nr = l & 63;
            int j = j0 + jj;
            Bs[jj * 65 + nr] = (j < CIN) ? Wp[(long)j * DM + n0 + nr] : 0.f;
        }
        __syncthreads();
        #pragma unroll
        for (int jj = 0; jj < 16; jj++) {
            float a[4], bb[4];
            #pragma unroll
            for (int r = 0; r < 4; r++) a[r] = As[(tr * 4 + r) * 17 + jj];
            #pragma unroll
            for (int cc = 0; cc < 4; cc++) bb[cc] = Bs[jj * 65 + tc * 4 + cc];
            #pragma unroll
            for (int r = 0; r < 4; r++)
                #pragma unroll
                for (int cc = 0; cc < 4; cc++) acc[r][cc] += a[r] * bb[cc];
        }
        __syncthreads();
    }
    #pragma unroll
    for (int r = 0; r < 4; r++) {
        int m = m0 + tr * 4 + r;
        #pragma unroll
        for (int cc = 0; cc < 4; cc++) {
            int n = n0 + tc * 4 + cc;
            g_Wd[(long)m * DM + n] = Whh[(long)m * DM + n] + acc[r][cc];
        }
    }
}

// ---------------- Gx = normalize(x) @ Wih^T  (24576 x 2048, K=321) ------------
// A[m,k] = (x[m*321+k]-mean[b,k])*istd[b,k], m = b*96+t. f32x2 micro-kernel.
__global__ __launch_bounds__(256) void gx_kernel(const float* __restrict__ x,
                                                 const float* __restrict__ Wih) {
    __shared__ float As[64 * 17];   // [m][k]
    __shared__ float Bs[16 * 66];   // [k][n] transposed, even pad
    int tid = threadIdx.x;
    int n0 = blockIdx.x * 64;       // 32 tiles
    int m0 = blockIdx.y * 64;       // 384 tiles
    int tr = tid >> 4, tc = tid & 15;
    unsigned long long acc[4][2] = {};
    for (int k0 = 0; k0 < CIN; k0 += 16) {
        #pragma unroll
        for (int i = 0; i < 4; i++) {
            int l = tid + 256 * i;
            int mr = l >> 4, kk = l & 15;
            int k = k0 + kk;
            int m = m0 + mr;
            float v = 0.f;
            if (k < CIN) {
                int b = m / TSEQ;
                int bc = b * CIN + k;
                v = (x[(long)m * CIN + k] - g_mean[bc]) * g_istd[bc];
            }
            As[mr * 17 + kk] = v;
        }
        #pragma unroll
        for (int i = 0; i < 4; i++) {
            int l = tid + 256 * i;
            int nr = l >> 4, kk = l & 15;
            int k = k0 + kk;
            Bs[kk * 66 + nr] = (k < CIN) ? Wih[(long)(n0 + nr) * CIN + k] : 0.f;
        }
        __syncthreads();
        #pragma unroll
        for (int kk = 0; kk < 16; kk++) {
            unsigned long long a[4];
            #pragma unroll
            for (int r = 0; r < 4; r++) a[r] = dup2(As[(tr * 4 + r) * 17 + kk]);
            const unsigned long long* wrow =
                reinterpret_cast<const unsigned long long*>(&Bs[kk * 66 + tc * 4]);
            unsigned long long w0 = wrow[0], w1 = wrow[1];
            #pragma unroll
            for (int r = 0; r < 4; r++) { fma2(acc[r][0], a[r], w0); fma2(acc[r][1], a[r], w1); }
        }
        __syncthreads();
    }
    #pragma unroll
    for (int r = 0; r < 4; r++) {
        int m = m0 + tr * 4 + r;
        float* dst = g_Gx + (long)m * G4 + n0 + tc * 4;
        dst[0] = lo32(acc[r][0]); dst[1] = hi32(acc[r][0]);
        dst[2] = lo32(acc[r][1]); dst[3] = hi32(acc[r][1]);
    }
}

// ---------------- LSTM step: g = h@W^T + pre + bias; gates; update h,c --------
// Block tile: 32 batch rows x (4 gates x 32 j). Grid (8, 16). 256 threads.
__global__ __launch_bounds__(256) void step_kernel(const float* __restrict__ hin,
                                                   float* __restrict__ hout,
                                                   float* __restrict__ cst,
                                                   const float* __restrict__ W,     // [2048][512]
                                                   const float* __restrict__ pre,   // nullable
                                                   long preStride,
                                                   const float* __restrict__ bias,  // [2048]
                                                   float* __restrict__ hstore) {    // nullable
    __shared__ float sm[32 * 33 + 32 * 130];   // hs | ws ; reused as gsh[32][132]
    float* hs = sm;                // [32][33]
    float* ws = sm + 32 * 33;      // [kk][ncol], pad 130 (even)
    int tid = threadIdx.x;
    int b0 = blockIdx.x * 32;
    int j0 = blockIdx.y * 32;
    int tr = tid >> 5;             // warp id 0..7
    int tc = tid & 31;
    unsigned long long acc[4][2] = {};   // rows tr*4+r, cols tc*4 + {0,1},{2,3}

    for (int k0 = 0; k0 < DM; k0 += 32) {
        #pragma unroll
        for (int i = 0; i < 4; i++) {
            int l = tid + 256 * i;
            int row = l >> 5, kk = l & 31;
            hs[row * 33 + kk] = hin[(b0 + row) * DM + k0 + kk];
        }
        #pragma unroll
        for (int i = 0; i < 16; i++) {
            int ncol = tr + 8 * i;                 // 0..127, each once
            int gate = ncol >> 5, jj = ncol & 31;
            int ng = gate * DM + j0 + jj;
            ws[tc * 130 + ncol] = W[(long)ng * DM + k0 + tc];
        }
        __syncthreads();
        #pragma unroll
        for (int kk = 0; kk < 32; kk++) {
            unsigned long long a[4];
            #pragma unroll
            for (int r = 0; r < 4; r++) a[r] = dup2(hs[(tr * 4 + r) * 33 + kk]);
            const unsigned long long* wrow =
                reinterpret_cast<const unsigned long long*>(&ws[kk * 130 + tc * 4]);
            unsigned long long w0 = wrow[0], w1 = wrow[1];
            #pragma unroll
            for (int r = 0; r < 4; r++) { fma2(acc[r][0], a[r], w0); fma2(acc[r][1], a[r], w1); }
        }
        __syncthreads();
    }

    // epilogue phase 1: add pre + bias, stage g tile to smem
    float* gsh = sm;   // [32][132]
    #pragma unroll
    for (int r = 0; r < 4; r++) {
        int row = tr * 4 + r;
        int bglob = b0 + row;
        #pragma unroll
        for (int p = 0; p < 2; p++) {
            float v0 = lo32(acc[r][p]), v1 = hi32(acc[r][p]);
            int c0 = tc * 4 + 2 * p;
            int g0 = c0 >> 5, g1 = (c0 + 1) >> 5;
            int n0g = g0 * DM + j0 + (c0 & 31);
            int n1g = g1 * DM + j0 + ((c0 + 1) & 31);
            float a0 = bias[n0g], a1 = bias[n1g];
            if (pre) {
                a0 += pre[(long)bglob * preStride + n0g];
                a1 += pre[(long)bglob * preStride + n1g];
            }
            gsh[row * 132 + c0] = v0 + a0;
            gsh[row * 132 + c0 + 1] = v1 + a1;
        }
    }
    __syncthreads();

    // epilogue phase 2: gate math, update c/h
    #pragma unroll
    for (int i = 0; i < 4; i++) {
        int cell = tid + 256 * i;
        int row = cell >> 5, jj = cell & 31;
        float iv = gsh[row * 132 + jj];
        float fv = gsh[row * 132 + 32 + jj];
        float gv = gsh[row * 132 + 64 + jj];
        float ov = gsh[row * 132 + 96 + jj];
        int idx = (b0 + row) * DM + j0 + jj;
        float co = cst[idx];
        float cn = sigf(fv) * co + sigf(iv) * tanhf(gv);
        float hn = sigf(ov) * tanhf(cn);
        cst[idx] = cn;
        hout[idx] = hn;
        if (hstore) hstore[idx] = hn;
    }
}

// ---------------- init h, c to zero ------------------------------------------
__global__ __launch_bounds__(256) void init_kernel() {
    int i = blockIdx.x * 256 + threadIdx.x;
    if (i < HD) { g_h[i] = 0.f; g_c[i] = 0.f; }
}

// ---------------- out: Y = Hdec @ Wp^T + bp, denormalize, scatter -------------
// A = g_Hdec (24576 x 512), m = t*256 + b. N = 321.
__global__ __launch_bounds__(256) void out_kernel(const float* __restrict__ Wp,
                                                  const float* __restrict__ bp,
                                                  float* __restrict__ out) {
    __shared__ float As[64 * 17];
    __shared__ float Bs[16 * 66];
    int tid = threadIdx.x;
    int n0 = blockIdx.x * 64;    // 6 tiles (guard n<321)
    int m0 = blockIdx.y * 64;    // 384 tiles
    int tr = tid >> 4, tc = tid & 15;
    unsigned long long acc[4][2] = {};
    for (int k0 = 0; k0 < DM; k0 += 16) {
        #pragma unroll
        for (int i = 0; i < 4; i++) {
            int l = tid + 256 * i;
            int mr = l >> 4, kk = l & 15;
            As[mr * 17 + kk] = g_Hdec[(long)(m0 + mr) * DM + k0 + kk];
        }
        #pragma unroll
        for (int i = 0; i < 4; i++) {
            int l = tid + 256 * i;
            int nr = l >> 4, kk = l & 15;
            int n = n0 + nr;
            Bs[kk * 66 + nr] = (n < CIN) ? Wp[(long)n * DM + k0 + kk] : 0.f;
        }
        __syncthreads();
        #pragma unroll
        for (int kk = 0; kk < 16; kk++) {
            unsigned long long a[4];
            #pragma unroll
            for (int r = 0; r < 4; r++) a[r] = dup2(As[(tr * 4 + r) * 17 + kk]);
            const unsigned long long* wrow =
                reinterpret_cast<const unsigned long long*>(&Bs[kk * 66 + tc * 4]);
            unsigned long long w0 = wrow[0], w1 = wrow[1];
            #pragma unroll
            for (int r = 0; r < 4; r++) { fma2(acc[r][0], a[r], w0); fma2(acc[r][1], a[r], w1); }
        }
        __syncthreads();
    }
    #pragma unroll
    for (int r = 0; r < 4; r++) {
        int m = m0 + tr * 4 + r;
        int t = m >> 8, b = m & 255;
        float vals[4] = { lo32(acc[r][0]), hi32(acc[r][0]), lo32(acc[r][1]), hi32(acc[r][1]) };
        #pragma unroll
        for (int cc = 0; cc < 4; cc++) {
            int n = n0 + tc * 4 + cc;
            if (n < CIN) {
                int bc = b * CIN + n;
                out[(long)b * PRED * CIN + (long)t * CIN + n] =
                    (vals[cc] + bp[n]) * g_std[bc] + g_mean[bc];
            }
        }
    }
}

// ---------------- host launcher ----------------------------------------------
extern "C" void kernel_launch(void* const* d_in, const int* in_sizes, int n_in,
                              void* d_out, int out_size) {
    const float* x   = (const float*)d_in[0];
    const float* Wih = (const float*)d_in[1];
    const float* Whh = (const float*)d_in[2];
    const float* bih = (const float*)d_in[3];
    const float* bhh = (const float*)d_in[4];
    const float* Wp  = (const float*)d_in[5];
    const float* bp  = (const float*)d_in[6];
    float* out = (float*)d_out;

    float *hbuf, *cbuf, *gx, *wd, *bd, *benc, *hdec;
    cudaGetSymbolAddress((void**)&hbuf, g_h);
    cudaGetSymbolAddress((void**)&cbuf, g_c);
    cudaGetSymbolAddress((void**)&gx,   g_Gx);
    cudaGetSymbolAddress((void**)&wd,   g_Wd);
    cudaGetSymbolAddress((void**)&bd,   g_bd);
    cudaGetSymbolAddress((void**)&benc, g_benc);
    cudaGetSymbolAddress((void**)&hdec, g_Hdec);

    stats_kernel<<<(BATCH * CIN + 255) / 256, 256>>>(x);
    bias_kernel<<<(G4 + 255) / 256, 256>>>(bih, bhh, Wih, bp);
    wd_kernel<<<dim3(DM / 64, G4 / 64), 256>>>(Wih, Wp, Whh);
    gx_kernel<<<dim3(G4 / 64, (BATCH * TSEQ) / 64), 256>>>(x, Wih);
    init_kernel<<<HD / 256, 256>>>();

    // 96 encoder updates + 95 decoder updates; outputs y_d = proj(h entering dec step d)
    for (int s = 0; s < TSEQ + PRED - 1; s++) {
        const float* hin = hbuf + (s & 1) * HD;
        float* hout = hbuf + ((s + 1) & 1) * HD;
        bool enc = (s < TSEQ);
        const float* W    = enc ? Whh : wd;
        const float* pre  = enc ? (gx + (long)s * G4) : nullptr;
        long stride       = enc ? (long)TSEQ * G4 : 0;
        const float* bias = enc ? benc : bd;
        float* hst = (s >= TSEQ - 1) ? (hdec + (long)(s - (TSEQ - 1)) * HD) : nullptr;
        step_kernel<<<dim3(BATCH / 32, DM / 32), 256>>>(hin, hout, cbuf, W, pre, stride, bias, hst);
    }

    out_kernel<<<dim3(6, (PRED * BATCH) / 64), 256>>>(Wp, bp, out);
    (void)in_sizes; (void)n_in; (void)out_size;
}

// round 4
// speedup vs baseline: 1.7680x; 1.7680x over previous
#include <cuda_runtime.h>
#include <cuda_bf16.h>
#include <math.h>
#include <stdint.h>

#define BATCH 256
#define TSEQ  96
#define PRED  96
#define CIN   321
#define DM    512
#define G4    2048
#define HD    (BATCH*DM)

#define PADC  72               // padded K cols (144B rows -> conflict-free ldmatrix)
#define AIMG  (256*PADC*2)     // 36864 B per (par,chunk,split)
#define WIMG  (64*PADC*2)      // 9216 B per (ntile,chunk,split)

// ---------------- device scratch ----------------------------------------------
__device__ float g_mean[BATCH*CIN];
__device__ float g_std [BATCH*CIN];
__device__ float g_istd[BATCH*CIN];
__device__ float g_Gx  [(size_t)BATCH*TSEQ*G4];
__device__ float g_Wd  [G4*DM];
__device__ float g_bd  [G4];
__device__ float g_benc[G4];
__device__ float g_c   [HD];
__device__ float g_Hdec[(size_t)PRED*HD];
// bf16 hidden images: [par2][chunk8][split2][256][72]
__device__ __align__(1024) unsigned char g_Hbf[2*8*2*AIMG];
// W images (gate-grouped, split): [ntile32][chunk8][split2][64][72]
__device__ __align__(1024) unsigned char g_WTe[32*8*2*WIMG];
__device__ __align__(1024) unsigned char g_WTd[32*8*2*WIMG];

// ---------------- helpers ------------------------------------------------------
__device__ __forceinline__ float sigf(float x) { return 1.f / (1.f + expf(-x)); }

__device__ __forceinline__ unsigned long long dup2(float x) {
    unsigned long long r;
    asm("mov.b64 %0, {%1, %2};" : "=l"(r) : "f"(x), "f"(x));
    return r;
}
__device__ __forceinline__ void fma2(unsigned long long& d, unsigned long long a, unsigned long long b) {
    asm("fma.rn.f32x2 %0, %1, %2, %0;" : "+l"(d) : "l"(a), "l"(b));
}
__device__ __forceinline__ float lo32(unsigned long long v) { return __uint_as_float((unsigned)v); }
__device__ __forceinline__ float hi32(unsigned long long v) { return __uint_as_float((unsigned)(v >> 32)); }

__device__ __forceinline__ uint32_t smem_u32(const void* p) {
    uint32_t a;
    asm("{ .reg .u64 t; cvta.to.shared.u64 t, %1; cvt.u32.u64 %0, t; }" : "=r"(a) : "l"(p));
    return a;
}
__device__ __forceinline__ void cpasync16(uint32_t dst, const void* src) {
    asm volatile("cp.async.cg.shared.global [%0], [%1], 16;" :: "r"(dst), "l"(src) : "memory");
}
#define CP_COMMIT() asm volatile("cp.async.commit_group;" ::: "memory")
#define CP_WAIT(N)  asm volatile("cp.async.wait_group %0;" :: "n"(N) : "memory")

__device__ __forceinline__ void ldsm4(uint32_t* r, uint32_t addr) {
    asm volatile("ldmatrix.sync.aligned.m8n8.x4.shared.b16 {%0,%1,%2,%3}, [%4];"
        : "=r"(r[0]), "=r"(r[1]), "=r"(r[2]), "=r"(r[3]) : "r"(addr));
}
__device__ __forceinline__ void mma16816(float* d, const uint32_t* a, const uint32_t* b) {
    asm volatile("mma.sync.aligned.m16n8k16.row.col.f32.bf16.bf16.f32 "
        "{%0,%1,%2,%3}, {%4,%5,%6,%7}, {%8,%9}, {%0,%1,%2,%3};"
        : "+f"(d[0]), "+f"(d[1]), "+f"(d[2]), "+f"(d[3])
        : "r"(a[0]), "r"(a[1]), "r"(a[2]), "r"(a[3]), "r"(b[0]), "r"(b[1]));
}

// ---------------- stats --------------------------------------------------------
__global__ __launch_bounds__(256) void stats_kernel(const float* __restrict__ x) {
    int idx = blockIdx.x * 256 + threadIdx.x;
    if (idx >= BATCH * CIN) return;
    int b = idx / CIN, ch = idx % CIN;
    float s = 0.f, ss = 0.f;
    const float* p = x + (size_t)b * TSEQ * CIN + ch;
    #pragma unroll 4
    for (int t = 0; t < TSEQ; t++) { float v = p[t * CIN]; s += v; ss += v * v; }
    float mean = s * (1.f / TSEQ);
    float var = ss * (1.f / TSEQ) - mean * mean;
    if (var < 0.f) var = 0.f;
    float sd = sqrtf(var + 1e-5f);
    g_mean[idx] = mean; g_std[idx] = sd; g_istd[idx] = 1.f / sd;
}

// ---------------- bias fold ----------------------------------------------------
__global__ __launch_bounds__(256) void bias_kernel(const float* __restrict__ bih,
                                                   const float* __restrict__ bhh,
                                                   const float* __restrict__ Wih,
                                                   const float* __restrict__ bp) {
    int n = blockIdx.x * 256 + threadIdx.x;
    if (n >= G4) return;
    float be = bih[n] + bhh[n];
    float s = 0.f;
    const float* w = Wih + (size_t)n * CIN;
    for (int j = 0; j < CIN; j++) s += w[j] * bp[j];
    g_benc[n] = be;
    g_bd[n] = be + s;
}

// ---------------- Wd = Whh + Wih @ Wp ------------------------------------------
__global__ __launch_bounds__(256) void wd_kernel(const float* __restrict__ Wih,
                                                 const float* __restrict__ Wp,
                                                 const float* __restrict__ Whh) {
    __shared__ float As[64 * 17];
    __shared__ float Bs[16 * 65];
    int tid = threadIdx.x;
    int n0 = blockIdx.x * 64;
    int m0 = blockIdx.y * 64;
    int tr = tid >> 4, tc = tid & 15;
    float acc[4][4] = {};
    for (int j0 = 0; j0 < CIN; j0 += 16) {
        #pragma unroll
        for (int i = 0; i < 4; i++) {
            int l = tid + 256 * i;
            int mr = l >> 4, jj = l & 15;
            int j = j0 + jj;
            As[mr * 17 + jj] = (j < CIN) ? Wih[(size_t)(m0 + mr) * CIN + j] : 0.f;
        }
        #pragma unroll
        for (int i = 0; i < 4; i++) {
            int l = tid + 256 * i;
            int jj = l >> 6, nr = l & 63;
            int j = j0 + jj;
            Bs[jj * 65 + nr] = (j < CIN) ? Wp[(size_t)j * DM + n0 + nr] : 0.f;
        }
        __syncthreads();
        #pragma unroll
        for (int jj = 0; jj < 16; jj++) {
            float a[4], bb[4];
            #pragma unroll
            for (int r = 0; r < 4; r++) a[r] = As[(tr * 4 + r) * 17 + jj];
            #pragma unroll
            for (int cc = 0; cc < 4; cc++) bb[cc] = Bs[jj * 65 + tc * 4 + cc];
            #pragma unroll
            for (int r = 0; r < 4; r++)
                #pragma unroll
                for (int cc = 0; cc < 4; cc++) acc[r][cc] += a[r] * bb[cc];
        }
        __syncthreads();
    }
    #pragma unroll
    for (int r = 0; r < 4; r++) {
        int m = m0 + tr * 4 + r;
        #pragma unroll
        for (int cc = 0; cc < 4; cc++) {
            int n = n0 + tc * 4 + cc;
            g_Wd[(size_t)m * DM + n] = Whh[(size_t)m * DM + n] + acc[r][cc];
        }
    }
}

// ---------------- Gx = normalize(x) @ Wih^T (FFMA2) ----------------------------
__global__ __launch_bounds__(256) void gx_kernel(const float* __restrict__ x,
                                                 const float* __restrict__ Wih) {
    __shared__ float As[64 * 17];
    __shared__ float Bs[16 * 66];
    int tid = threadIdx.x;
    int n0 = blockIdx.x * 64;
    int m0 = blockIdx.y * 64;
    int tr = tid >> 4, tc = tid & 15;
    unsigned long long acc[4][2] = {};
    for (int k0 = 0; k0 < CIN; k0 += 16) {
        #pragma unroll
        for (int i = 0; i < 4; i++) {
            int l = tid + 256 * i;
            int mr = l >> 4, kk = l & 15;
            int k = k0 + kk;
            int m = m0 + mr;
            float v = 0.f;
            if (k < CIN) {
                int b = m / TSEQ;
                int bc = b * CIN + k;
                v = (x[(size_t)m * CIN + k] - g_mean[bc]) * g_istd[bc];
            }
            As[mr * 17 + kk] = v;
        }
        #pragma unroll
        for (int i = 0; i < 4; i++) {
            int l = tid + 256 * i;
            int nr = l >> 4, kk = l & 15;
            int k = k0 + kk;
            Bs[kk * 66 + nr] = (k < CIN) ? Wih[(size_t)(n0 + nr) * CIN + k] : 0.f;
        }
        __syncthreads();
        #pragma unroll
        for (int kk = 0; kk < 16; kk++) {
            unsigned long long a[4];
            #pragma unroll
            for (int r = 0; r < 4; r++) a[r] = dup2(As[(tr * 4 + r) * 17 + kk]);
            const unsigned long long* wrow =
                reinterpret_cast<const unsigned long long*>(&Bs[kk * 66 + tc * 4]);
            unsigned long long w0 = wrow[0], w1 = wrow[1];
            #pragma unroll
            for (int r = 0; r < 4; r++) { fma2(acc[r][0], a[r], w0); fma2(acc[r][1], a[r], w1); }
        }
        __syncthreads();
    }
    #pragma unroll
    for (int r = 0; r < 4; r++) {
        int m = m0 + tr * 4 + r;
        float* dst = g_Gx + (size_t)m * G4 + n0 + tc * 4;
        dst[0] = lo32(acc[r][0]); dst[1] = hi32(acc[r][0]);
        dst[2] = lo32(acc[r][1]); dst[3] = hi32(acc[r][1]);
    }
}

// ---------------- W image builder: gate-grouped, bf16 split, padded ------------
// dst[(ntile*8+chunk)*2 + split][64][72] bf16; tile row rr = gate*16 + jj
__global__ __launch_bounds__(256) void wsplit_kernel(const float* __restrict__ src,
                                                     unsigned char* __restrict__ dst) {
    int chunk = blockIdx.x;   // 0..7
    int ntile = blockIdx.y;   // 0..31
    int tid = threadIdx.x;
    int rr = tid >> 2;        // 0..63
    int q  = tid & 3;         // col group of 18
    int gate = rr >> 4, jj = rr & 15;
    int srow = gate * DM + ntile * 16 + jj;
    unsigned char* d0 = dst + ((size_t)(ntile * 8 + chunk) * 2) * WIMG;
    #pragma unroll
    for (int c = 0; c < 18; c++) {
        int col = q * 18 + c;
        float v = (col < 64) ? src[(size_t)srow * DM + chunk * 64 + col] : 0.f;
        __nv_bfloat16 hb = __float2bfloat16(v);
        float rem = v - __bfloat162float(hb);
        __nv_bfloat16 lb = __float2bfloat16(rem);
        size_t off = (size_t)rr * 144 + col * 2;
        *(__nv_bfloat16*)(d0 + off)        = hb;
        *(__nv_bfloat16*)(d0 + WIMG + off) = lb;
    }
}

// ---------------- init: zero c and h images ------------------------------------
__global__ __launch_bounds__(256) void init_kernel() {
    int i = blockIdx.x * 256 + threadIdx.x;
    if (i < HD) g_c[i] = 0.f;
    if (i < (int)(sizeof(g_Hbf) / 4)) ((uint32_t*)g_Hbf)[i] = 0u;
}

// ---------------- mma.sync LSTM step -------------------------------------------
// grid (32 ntiles, 4 mq), 128 threads (4 warps, warp tile 16 x 64)
#define STAGE 36864
#define STEP_SMEM (2*STAGE)

__global__ void __launch_bounds__(128, 1) step_kernel(int par,
                                                      const unsigned char* __restrict__ Wt,
                                                      const float* __restrict__ pre,
                                                      const float* __restrict__ bias,
                                                      float* __restrict__ hstore) {
    extern __shared__ unsigned char smem[];
    const int tid = threadIdx.x;
    const int w = tid >> 5, lane = tid & 31;
    const int ntile = blockIdx.x;
    const int mq = blockIdx.y;
    uint32_t sbase = smem_u32(smem);

    float acc[8][4];
    #pragma unroll
    for (int f = 0; f < 8; f++)
        #pragma unroll
        for (int r = 0; r < 4; r++) acc[f][r] = 0.f;

    // per-lane ldmatrix offsets
    const uint32_t aoff = (uint32_t)((w * 16 + (lane & 15)) * 144 + (lane >> 4) * 16);
    const uint32_t boff = (uint32_t)((((lane >> 4) & 1) * 8 + (lane & 7)) * 144 + ((lane >> 3) & 1) * 16);

    const unsigned char* Abase = g_Hbf + ((size_t)(par * 8) * 2) * AIMG;
    const unsigned char* Bbase = Wt + ((size_t)(ntile * 8) * 2) * WIMG;

    // issue chunk copy helper (18 x 16B per thread)
    auto issue = [&](int chunk, int buf) {
        uint32_t sb = sbase + buf * STAGE;
        #pragma unroll
        for (int i = 0; i < 18; i++) {
            int idx = tid + i * 128;             // 0..2303
            int region = idx / 576;
            int off = (idx % 576) * 16;
            uint32_t dst = sb + region * 9216 + off;
            const unsigned char* src;
            if (region < 2)
                src = Abase + ((size_t)(chunk * 2 + region)) * AIMG + mq * 9216 + off;
            else
                src = Bbase + ((size_t)(chunk * 2 + (region - 2))) * WIMG + off;
            cpasync16(dst, src);
        }
        CP_COMMIT();
    };

    issue(0, 0);
    #pragma unroll 1
    for (int c = 0; c < 8; c++) {
        if (c < 7) { issue(c + 1, (c + 1) & 1); CP_WAIT(1); }
        else       { CP_WAIT(0); }
        __syncthreads();
        uint32_t st = sbase + (c & 1) * STAGE;
        uint32_t sAhi = st, sAlo = st + 9216, sWhi = st + 18432, sWlo = st + 27648;
        #pragma unroll
        for (int kf = 0; kf < 4; kf++) {
            uint32_t ah[4], al[4];
            ldsm4(ah, sAhi + aoff + kf * 32);
            ldsm4(al, sAlo + aoff + kf * 32);
            #pragma unroll
            for (int ng = 0; ng < 4; ng++) {
                uint32_t bh[4], bl[4];
                uint32_t ba = boff + ng * 2304 + kf * 32;
                ldsm4(bh, sWhi + ba);
                ldsm4(bl, sWlo + ba);
                mma16816(acc[2 * ng],     ah, bh);
                mma16816(acc[2 * ng + 1], ah, bh + 2);
                mma16816(acc[2 * ng],     ah, bl);
                mma16816(acc[2 * ng + 1], ah, bl + 2);
                mma16816(acc[2 * ng],     al, bh);
                mma16816(acc[2 * ng + 1], al, bh + 2);
            }
        }
        __syncthreads();
    }

    // ---------------- epilogue: gates, c/h update, next A image ----------------
    const int chunkA = ntile >> 2;
    unsigned char* imgHi = g_Hbf + ((size_t)(((par ^ 1) * 8 + chunkA) * 2)) * AIMG;
    unsigned char* imgLo = imgHi + AIMG;

    #pragma unroll
    for (int fh = 0; fh < 2; fh++) {
        int jl0 = fh * 8 + (lane & 3) * 2;
        int j0g = ntile * 16 + jl0;
        float bi0 = bias[j0g],        bi1 = bias[j0g + 1];
        float bf0 = bias[512 + j0g],  bf1 = bias[512 + j0g + 1];
        float bg0 = bias[1024 + j0g], bg1 = bias[1024 + j0g + 1];
        float bo0 = bias[1536 + j0g], bo1 = bias[1536 + j0g + 1];
        #pragma unroll
        for (int rowi = 0; rowi < 2; rowi++) {
            int rloc = w * 16 + (lane >> 2) + rowi * 8;
            int b = mq * 64 + rloc;
            float h2[2];
            #pragma unroll
            for (int cp = 0; cp < 2; cp++) {
                int j = j0g + cp;
                int reg = rowi * 2 + cp;
                float gi = acc[fh][reg]     + (cp ? bi1 : bi0);
                float gf = acc[2 + fh][reg] + (cp ? bf1 : bf0);
                float gg = acc[4 + fh][reg] + (cp ? bg1 : bg0);
                float go = acc[6 + fh][reg] + (cp ? bo1 : bo0);
                if (pre) {
                    const float* pb = pre + (size_t)b * (TSEQ * G4);
                    gi += pb[j]; gf += pb[512 + j]; gg += pb[1024 + j]; go += pb[1536 + j];
                }
                size_t ci = (size_t)b * DM + j;
                float cn = sigf(gf) * g_c[ci] + sigf(gi) * tanhf(gg);
                float hn = sigf(go) * tanhf(cn);
                g_c[ci] = cn;
                if (hstore) hstore[ci] = hn;
                h2[cp] = hn;
            }
            // pack pair into next-step A image (hi/lo bf16)
            __nv_bfloat16 h0 = __float2bfloat16(h2[0]);
            __nv_bfloat16 h1 = __float2bfloat16(h2[1]);
            float r0 = h2[0] - __bfloat162float(h0);
            float r1 = h2[1] - __bfloat162float(h1);
            __nv_bfloat16 l0 = __float2bfloat16(r0);
            __nv_bfloat16 l1 = __float2bfloat16(r1);
            uint32_t hw = (uint32_t)__bfloat16_as_ushort(h0) | ((uint32_t)__bfloat16_as_ushort(h1) << 16);
            uint32_t lw = (uint32_t)__bfloat16_as_ushort(l0) | ((uint32_t)__bfloat16_as_ushort(l1) << 16);
            size_t colA = (size_t)((ntile & 3) * 16 + jl0);
            size_t off = (size_t)b * 144 + colA * 2;
            *(uint32_t*)(imgHi + off) = hw;
            *(uint32_t*)(imgLo + off) = lw;
        }
    }
}

// ---------------- out: Y = Hdec @ Wp^T + bp, denormalize -----------------------
__global__ __launch_bounds__(256) void out_kernel(const float* __restrict__ Wp,
                                                  const float* __restrict__ bp,
                                                  float* __restrict__ out) {
    __shared__ float As[64 * 17];
    __shared__ float Bs[16 * 66];
    int tid = threadIdx.x;
    int n0 = blockIdx.x * 64;
    int m0 = blockIdx.y * 64;
    int tr = tid >> 4, tc = tid & 15;
    unsigned long long acc[4][2] = {};
    for (int k0 = 0; k0 < DM; k0 += 16) {
        #pragma unroll
        for (int i = 0; i < 4; i++) {
            int l = tid + 256 * i;
            int mr = l >> 4, kk = l & 15;
            As[mr * 17 + kk] = g_Hdec[(size_t)(m0 + mr) * DM + k0 + kk];
        }
        #pragma unroll
        for (int i = 0; i < 4; i++) {
            int l = tid + 256 * i;
            int nr = l >> 4, kk = l & 15;
            int n = n0 + nr;
            Bs[kk * 66 + nr] = (n < CIN) ? Wp[(size_t)n * DM + k0 + kk] : 0.f;
        }
        __syncthreads();
        #pragma unroll
        for (int kk = 0; kk < 16; kk++) {
            unsigned long long a[4];
            #pragma unroll
            for (int r = 0; r < 4; r++) a[r] = dup2(As[(tr * 4 + r) * 17 + kk]);
            const unsigned long long* wrow =
                reinterpret_cast<const unsigned long long*>(&Bs[kk * 66 + tc * 4]);
            unsigned long long w0 = wrow[0], w1 = wrow[1];
            #pragma unroll
            for (int r = 0; r < 4; r++) { fma2(acc[r][0], a[r], w0); fma2(acc[r][1], a[r], w1); }
        }
        __syncthreads();
    }
    #pragma unroll
    for (int r = 0; r < 4; r++) {
        int m = m0 + tr * 4 + r;
        int t = m >> 8, b = m & 255;
        float vals[4] = { lo32(acc[r][0]), hi32(acc[r][0]), lo32(acc[r][1]), hi32(acc[r][1]) };
        #pragma unroll
        for (int cc = 0; cc < 4; cc++) {
            int n = n0 + tc * 4 + cc;
            if (n < CIN) {
                int bc = b * CIN + n;
                out[(size_t)b * PRED * CIN + (size_t)t * CIN + n] =
                    (vals[cc] + bp[n]) * g_std[bc] + g_mean[bc];
            }
        }
    }
}

// ---------------- host launcher ------------------------------------------------
extern "C" void kernel_launch(void* const* d_in, const int* in_sizes, int n_in,
                              void* d_out, int out_size) {
    const float* x   = (const float*)d_in[0];
    const float* Wih = (const float*)d_in[1];
    const float* Whh = (const float*)d_in[2];
    const float* bih = (const float*)d_in[3];
    const float* bhh = (const float*)d_in[4];
    const float* Wp  = (const float*)d_in[5];
    const float* bp  = (const float*)d_in[6];
    float* out = (float*)d_out;

    float *gx, *wd, *bd, *benc, *hdec;
    unsigned char *wte, *wtd;
    cudaGetSymbolAddress((void**)&gx,   g_Gx);
    cudaGetSymbolAddress((void**)&wd,   g_Wd);
    cudaGetSymbolAddress((void**)&bd,   g_bd);
    cudaGetSymbolAddress((void**)&benc, g_benc);
    cudaGetSymbolAddress((void**)&hdec, g_Hdec);
    cudaGetSymbolAddress((void**)&wte,  g_WTe);
    cudaGetSymbolAddress((void**)&wtd,  g_WTd);

    cudaFuncSetAttribute(step_kernel, cudaFuncAttributeMaxDynamicSharedMemorySize, STEP_SMEM);

    stats_kernel<<<(BATCH * CIN + 255) / 256, 256>>>(x);
    bias_kernel<<<(G4 + 255) / 256, 256>>>(bih, bhh, Wih, bp);
    wd_kernel<<<dim3(DM / 64, G4 / 64), 256>>>(Wih, Wp, Whh);
    gx_kernel<<<dim3(G4 / 64, (BATCH * TSEQ) / 64), 256>>>(x, Wih);
    wsplit_kernel<<<dim3(8, 32), 256>>>(Whh, wte);
    wsplit_kernel<<<dim3(8, 32), 256>>>(wd, wtd);
    {
        int nthr = (int)(sizeof(g_Hbf) / 4);
        init_kernel<<<(nthr + 255) / 256, 256>>>();
    }

    for (int s = 0; s < TSEQ + PRED - 1; s++) {
        bool enc = (s < TSEQ);
        int par = s & 1;
        const unsigned char* Wt = enc ? wte : wtd;
        const float* pre  = enc ? (gx + (size_t)s * G4) : nullptr;
        const float* bias = enc ? benc : bd;
        float* hst = (s >= TSEQ - 1) ? (hdec + (size_t)(s - (TSEQ - 1)) * HD) : nullptr;
        step_kernel<<<dim3(32, 4), 128, STEP_SMEM>>>(par, Wt, pre, bias, hst);
    }

    out_kernel<<<dim3(6, (PRED * BATCH) / 64), 256>>>(Wp, bp, out);
    (void)in_sizes; (void)n_in; (void)out_size;
}

// round 5
// speedup vs baseline: 2.5453x; 1.4396x over previous
#include <cuda_runtime.h>
#include <cuda_bf16.h>
#include <math.h>
#include <stdint.h>

#define BATCH 256
#define TSEQ  96
#define PRED  96
#define CIN   321
#define DM    512
#define G4    2048
#define HD    (BATCH*DM)

#define AIMG  36864u            // 256 rows x 144 B (72 bf16 cols) per (chunk,split)
#define WIMG  9216u             // 64 rows x 144 B per (chunk,split)
#define XIMG  (24576u*144u)     // x image per (chunk,split)

// ---------------- device scratch ----------------------------------------------
__device__ float g_mean[BATCH*CIN];
__device__ float g_std [BATCH*CIN];
__device__ float g_istd[BATCH*CIN];
__device__ float g_Gx  [(size_t)BATCH*TSEQ*G4];
__device__ float g_Wd  [G4*DM];
__device__ float g_bd  [G4];
__device__ float g_benc[G4];
__device__ float g_c   [HD];
__device__ float g_Hdec[(size_t)PRED*HD];
// bf16 hidden images: [par2][chunk8][split2][256][72]
__device__ __align__(1024) unsigned char g_Hbf[2*8*2*AIMG];
// recurrent W images (gate-interleaved rows, split): [ntile32][chunk8][split2][64][72]
__device__ __align__(1024) unsigned char g_WTe[32*8*2*WIMG];
__device__ __align__(1024) unsigned char g_WTd[32*8*2*WIMG];
// gx operand images: x [chunk6][split2][24576][72], Wih [ntile32][chunk6][split2][64][72]
__device__ __align__(1024) unsigned char g_Xbf[6*2*XIMG];
__device__ __align__(1024) unsigned char g_WIe[32*6*2*WIMG];

// ---------------- helpers ------------------------------------------------------
__device__ __forceinline__ float sigf(float x) { return 1.f / (1.f + expf(-x)); }

__device__ __forceinline__ unsigned long long dup2(float x) {
    unsigned long long r;
    asm("mov.b64 %0, {%1, %2};" : "=l"(r) : "f"(x), "f"(x));
    return r;
}
__device__ __forceinline__ void fma2(unsigned long long& d, unsigned long long a, unsigned long long b) {
    asm("fma.rn.f32x2 %0, %1, %2, %0;" : "+l"(d) : "l"(a), "l"(b));
}
__device__ __forceinline__ float lo32(unsigned long long v) { return __uint_as_float((unsigned)v); }
__device__ __forceinline__ float hi32(unsigned long long v) { return __uint_as_float((unsigned)(v >> 32)); }

__device__ __forceinline__ uint32_t smem_u32(const void* p) {
    uint32_t a;
    asm("{ .reg .u64 t; cvta.to.shared.u64 t, %1; cvt.u32.u64 %0, t; }" : "=r"(a) : "l"(p));
    return a;
}
__device__ __forceinline__ void cpasync16(uint32_t dst, const void* src) {
    asm volatile("cp.async.cg.shared.global [%0], [%1], 16;" :: "r"(dst), "l"(src) : "memory");
}
#define CP_COMMIT() asm volatile("cp.async.commit_group;" ::: "memory")
#define CP_WAIT(N)  asm volatile("cp.async.wait_group %0;" :: "n"(N) : "memory")

__device__ __forceinline__ void ldsm4(uint32_t* r, uint32_t addr) {
    asm volatile("ldmatrix.sync.aligned.m8n8.x4.shared.b16 {%0,%1,%2,%3}, [%4];"
        : "=r"(r[0]), "=r"(r[1]), "=r"(r[2]), "=r"(r[3]) : "r"(addr));
}
__device__ __forceinline__ void mma16816(float* d, const uint32_t* a, const uint32_t* b) {
    asm volatile("mma.sync.aligned.m16n8k16.row.col.f32.bf16.bf16.f32 "
        "{%0,%1,%2,%3}, {%4,%5,%6,%7}, {%8,%9}, {%0,%1,%2,%3};"
        : "+f"(d[0]), "+f"(d[1]), "+f"(d[2]), "+f"(d[3])
        : "r"(a[0]), "r"(a[1]), "r"(a[2]), "r"(a[3]), "r"(b[0]), "r"(b[1]));
}
__device__ __forceinline__ void bfsplit2(float a, float b, uint32_t& hw, uint32_t& lw) {
    __nv_bfloat16 h0 = __float2bfloat16(a), h1 = __float2bfloat16(b);
    float r0 = a - __bfloat162float(h0), r1 = b - __bfloat162float(h1);
    __nv_bfloat16 l0 = __float2bfloat16(r0), l1 = __float2bfloat16(r1);
    hw = (uint32_t)__bfloat16_as_ushort(h0) | ((uint32_t)__bfloat16_as_ushort(h1) << 16);
    lw = (uint32_t)__bfloat16_as_ushort(l0) | ((uint32_t)__bfloat16_as_ushort(l1) << 16);
}

// ---------------- stats --------------------------------------------------------
__global__ __launch_bounds__(256) void stats_kernel(const float* __restrict__ x) {
    int idx = blockIdx.x * 256 + threadIdx.x;
    if (idx >= BATCH * CIN) return;
    int b = idx / CIN, ch = idx % CIN;
    float s = 0.f, ss = 0.f;
    const float* p = x + (size_t)b * TSEQ * CIN + ch;
    #pragma unroll 4
    for (int t = 0; t < TSEQ; t++) { float v = p[t * CIN]; s += v; ss += v * v; }
    float mean = s * (1.f / TSEQ);
    float var = ss * (1.f / TSEQ) - mean * mean;
    if (var < 0.f) var = 0.f;
    float sd = sqrtf(var + 1e-5f);
    g_mean[idx] = mean; g_std[idx] = sd; g_istd[idx] = 1.f / sd;
}

// ---------------- bias fold ----------------------------------------------------
__global__ __launch_bounds__(256) void bias_kernel(const float* __restrict__ bih,
                                                   const float* __restrict__ bhh,
                                                   const float* __restrict__ Wih,
                                                   const float* __restrict__ bp) {
    int n = blockIdx.x * 256 + threadIdx.x;
    if (n >= G4) return;
    float be = bih[n] + bhh[n];
    float s = 0.f;
    const float* w = Wih + (size_t)n * CIN;
    for (int j = 0; j < CIN; j++) s += w[j] * bp[j];
    g_benc[n] = be;
    g_bd[n] = be + s;
}

// ---------------- Wd = Whh + Wih @ Wp ------------------------------------------
__global__ __launch_bounds__(256) void wd_kernel(const float* __restrict__ Wih,
                                                 const float* __restrict__ Wp,
                                                 const float* __restrict__ Whh) {
    __shared__ float As[64 * 17];
    __shared__ float Bs[16 * 65];
    int tid = threadIdx.x;
    int n0 = blockIdx.x * 64;
    int m0 = blockIdx.y * 64;
    int tr = tid >> 4, tc = tid & 15;
    float acc[4][4] = {};
    for (int j0 = 0; j0 < CIN; j0 += 16) {
        #pragma unroll
        for (int i = 0; i < 4; i++) {
            int l = tid + 256 * i;
            int mr = l >> 4, jj = l & 15;
            int j = j0 + jj;
            As[mr * 17 + jj] = (j < CIN) ? Wih[(size_t)(m0 + mr) * CIN + j] : 0.f;
        }
        #pragma unroll
        for (int i = 0; i < 4; i++) {
            int l = tid + 256 * i;
            int jj = l >> 6, nr = l & 63;
            int j = j0 + jj;
            Bs[jj * 65 + nr] = (j < CIN) ? Wp[(size_t)j * DM + n0 + nr] : 0.f;
        }
        __syncthreads();
        #pragma unroll
        for (int jj = 0; jj < 16; jj++) {
            float a[4], bb[4];
            #pragma unroll
            for (int r = 0; r < 4; r++) a[r] = As[(tr * 4 + r) * 17 + jj];
            #pragma unroll
            for (int cc = 0; cc < 4; cc++) bb[cc] = Bs[jj * 65 + tc * 4 + cc];
            #pragma unroll
            for (int r = 0; r < 4; r++)
                #pragma unroll
                for (int cc = 0; cc < 4; cc++) acc[r][cc] += a[r] * bb[cc];
        }
        __syncthreads();
    }
    #pragma unroll
    for (int r = 0; r < 4; r++) {
        int m = m0 + tr * 4 + r;
        #pragma unroll
        for (int cc = 0; cc < 4; cc++) {
            int n = n0 + tc * 4 + cc;
            g_Wd[(size_t)m * DM + n] = Whh[(size_t)m * DM + n] + acc[r][cc];
        }
    }
}

// ---------------- recurrent W image builder ------------------------------------
// tile row rr = joct*32 + gate*8 + j7  (ntile j index jj = joct*8+j7)
__global__ __launch_bounds__(256) void wsplit_kernel(const float* __restrict__ src,
                                                     unsigned char* __restrict__ dst) {
    int chunk = blockIdx.x;   // 0..7
    int ntile = blockIdx.y;   // 0..31
    int tid = threadIdx.x;
    int rr = tid >> 2;        // 0..63
    int q  = tid & 3;
    int joct = rr >> 5, rem = rr & 31;
    int gate = rem >> 3, j7 = rem & 7;
    int srow = gate * DM + ntile * 16 + joct * 8 + j7;
    unsigned char* d0 = dst + ((size_t)(ntile * 8 + chunk) * 2) * WIMG;
    #pragma unroll
    for (int c = 0; c < 18; c++) {
        int col = q * 18 + c;
        float v = (col < 64) ? src[(size_t)srow * DM + chunk * 64 + col] : 0.f;
        __nv_bfloat16 hb = __float2bfloat16(v);
        float rem2 = v - __bfloat162float(hb);
        __nv_bfloat16 lb = __float2bfloat16(rem2);
        size_t off = (size_t)rr * 144 + col * 2;
        *(__nv_bfloat16*)(d0 + off)        = hb;
        *(__nv_bfloat16*)(d0 + WIMG + off) = lb;
    }
}

// ---------------- Wih image builder for gx (plain rows, K guard) ---------------
__global__ __launch_bounds__(256) void wihsplit_kernel(const float* __restrict__ Wih) {
    int chunk = blockIdx.x;   // 0..5
    int ntile = blockIdx.y;   // 0..31
    int tid = threadIdx.x;
    int rr = tid >> 2;
    int q  = tid & 3;
    int srow = ntile * 64 + rr;
    unsigned char* d0 = g_WIe + ((size_t)(ntile * 6 + chunk) * 2) * WIMG;
    #pragma unroll
    for (int c = 0; c < 18; c++) {
        int col = q * 18 + c;
        int k = chunk * 64 + col;
        float v = (col < 64 && k < CIN) ? Wih[(size_t)srow * CIN + k] : 0.f;
        __nv_bfloat16 hb = __float2bfloat16(v);
        float rem2 = v - __bfloat162float(hb);
        __nv_bfloat16 lb = __float2bfloat16(rem2);
        size_t off = (size_t)rr * 144 + col * 2;
        *(__nv_bfloat16*)(d0 + off)        = hb;
        *(__nv_bfloat16*)(d0 + WIMG + off) = lb;
    }
}

// ---------------- x normalize+split images -------------------------------------
__global__ __launch_bounds__(256) void xsplit_kernel(const float* __restrict__ x) {
    int idx = blockIdx.x * 256 + threadIdx.x;
    if (idx >= BATCH * TSEQ * CIN) return;
    int m = idx / CIN, k = idx - m * CIN;
    int b = m / TSEQ;
    int bc = b * CIN + k;
    float v = (x[idx] - g_mean[bc]) * g_istd[bc];
    __nv_bfloat16 hb = __float2bfloat16(v);
    float rem = v - __bfloat162float(hb);
    __nv_bfloat16 lb = __float2bfloat16(rem);
    int chunk = k >> 6, col = k & 63;
    size_t offh = ((size_t)(chunk * 2) * 24576 + m) * 144 + col * 2;
    *(__nv_bfloat16*)(g_Xbf + offh)        = hb;
    *(__nv_bfloat16*)(g_Xbf + offh + XIMG) = lb;
}

// ---------------- init: zero c and h images ------------------------------------
__global__ __launch_bounds__(256) void init_kernel() {
    int i = blockIdx.x * 256 + threadIdx.x;
    if (i < HD) g_c[i] = 0.f;
    if (i < (int)(sizeof(g_Hbf) / 4)) ((uint32_t*)g_Hbf)[i] = 0u;
}

// ---------------- gx = xnorm @ Wih^T via HMMA split ----------------------------
// grid (32 ntile, 192 mtile), 256 thr; block tile 128m x 64n, K=384 (6 chunks)
#define GXSTAGE 55296
#define GX_SMEM (2*GXSTAGE)
__global__ void __launch_bounds__(256, 1) gxmma_kernel() {
    extern __shared__ unsigned char smem[];
    const int tid = threadIdx.x;
    const int w = tid >> 5, lane = tid & 31;
    const int n0 = blockIdx.x * 64;
    const int m0 = blockIdx.y * 128;
    uint32_t sbase = smem_u32(smem);
    float acc[8][4];
    #pragma unroll
    for (int f = 0; f < 8; f++)
        #pragma unroll
        for (int r = 0; r < 4; r++) acc[f][r] = 0.f;

    const uint32_t aoff = (uint32_t)((w * 16 + (lane & 15)) * 144 + (lane >> 4) * 16);
    const uint32_t boff = (uint32_t)(((((lane >> 4) & 1) * 8) + (lane & 7)) * 144 + ((lane >> 3) & 1) * 16);
    const unsigned char* Bbase = g_WIe + ((size_t)blockIdx.x * 6 * 2) * WIMG;

    auto issue = [&](int chunk, int buf) {
        uint32_t sb = sbase + buf * GXSTAGE;
        #pragma unroll
        for (int i = 0; i < 14; i++) {
            int idx = tid + i * 256;
            if (idx >= 3456) break;
            uint32_t dst; const unsigned char* src;
            if (idx < 2304) {
                int sp = idx / 1152; int off = (idx - sp * 1152) * 16;
                dst = sb + sp * 18432 + off;
                src = g_Xbf + (size_t)(chunk * 2 + sp) * XIMG + (size_t)m0 * 144 + off;
            } else {
                int j = idx - 2304; int sp = j / 576; int off = (j - sp * 576) * 16;
                dst = sb + 36864 + sp * 9216 + off;
                src = Bbase + (size_t)(chunk * 2 + sp) * WIMG + off;
            }
            cpasync16(dst, src);
        }
        CP_COMMIT();
    };

    issue(0, 0); issue(1, 1);
    #pragma unroll 1
    for (int c = 0; c < 6; c++) {
        if (c < 5) { CP_WAIT(1); } else { CP_WAIT(0); }
        __syncthreads();
        uint32_t st = sbase + (c & 1) * GXSTAGE;
        uint32_t sAhi = st, sAlo = st + 18432, sWhi = st + 36864, sWlo = st + 46080;
        #pragma unroll
        for (int kf = 0; kf < 4; kf++) {
            uint32_t ah[4], al[4], bh[4][4], bl[4][4];
            ldsm4(ah, sAhi + aoff + kf * 32);
            ldsm4(al, sAlo + aoff + kf * 32);
            #pragma unroll
            for (int ng = 0; ng < 4; ng++) {
                ldsm4(bh[ng], sWhi + boff + ng * 2304 + kf * 32);
                ldsm4(bl[ng], sWlo + boff + ng * 2304 + kf * 32);
            }
            #pragma unroll
            for (int ng = 0; ng < 4; ng++) { mma16816(acc[2*ng], ah, bh[ng]); mma16816(acc[2*ng+1], ah, bh[ng]+2); }
            #pragma unroll
            for (int ng = 0; ng < 4; ng++) { mma16816(acc[2*ng], ah, bl[ng]); mma16816(acc[2*ng+1], ah, bl[ng]+2); }
            #pragma unroll
            for (int ng = 0; ng < 4; ng++) { mma16816(acc[2*ng], al, bh[ng]); mma16816(acc[2*ng+1], al, bh[ng]+2); }
        }
        __syncthreads();
        if (c + 2 < 6) issue(c + 2, c & 1);
    }
    #pragma unroll
    for (int f = 0; f < 8; f++) {
        int n = n0 + (f >> 1) * 16 + (f & 1) * 8 + (lane & 3) * 2;
        #pragma unroll
        for (int rowi = 0; rowi < 2; rowi++) {
            int m = m0 + w * 16 + (lane >> 2) + rowi * 8;
            *(float2*)&g_Gx[(size_t)m * G4 + n] = make_float2(acc[f][rowi*2], acc[f][rowi*2+1]);
        }
    }
}

// ---------------- HMMA LSTM step v2 --------------------------------------------
// grid (32 ntile, 4 mq), 256 thr (8 warps: wr=w&3 rows, wc=w>>2 col-half)
#define STAGE 36864
#define STEP_SMEM (3*STAGE)
__global__ void __launch_bounds__(256, 1) step_kernel(int par,
                                                      const unsigned char* __restrict__ Wt,
                                                      const float* __restrict__ pre,
                                                      const float* __restrict__ bias,
                                                      float* __restrict__ hstore) {
    extern __shared__ unsigned char smem[];
    const int tid = threadIdx.x;
    const int w = tid >> 5, lane = tid & 31;
    const int wr = w & 3, wc = w >> 2;
    const int ntile = blockIdx.x, mq = blockIdx.y;
    uint32_t sbase = smem_u32(smem);

    float acc[4][4];
    #pragma unroll
    for (int g = 0; g < 4; g++)
        #pragma unroll
        for (int r = 0; r < 4; r++) acc[g][r] = 0.f;

    const uint32_t aoff = (uint32_t)((wr * 16 + (lane & 15)) * 144 + (lane >> 4) * 16);
    const uint32_t boff = (uint32_t)((wc * 32 + ((lane >> 4) & 1) * 8 + (lane & 7)) * 144 + ((lane >> 3) & 1) * 16);

    const unsigned char* Abase = g_Hbf + ((size_t)(par * 8) * 2) * AIMG;
    const unsigned char* Bbase = Wt + ((size_t)(ntile * 8) * 2) * WIMG;

    auto issue = [&](int chunk, int buf) {
        uint32_t sb = sbase + buf * STAGE;
        #pragma unroll
        for (int i = 0; i < 9; i++) {
            int idx = tid + i * 256;
            int region = idx / 576;
            int off = (idx - region * 576) * 16;
            uint32_t dst = sb + region * 9216 + off;
            const unsigned char* src;
            if (region < 2) src = Abase + (size_t)(chunk * 2 + region) * AIMG + mq * 9216 + off;
            else            src = Bbase + (size_t)(chunk * 2 + (region - 2)) * WIMG + off;
            cpasync16(dst, src);
        }
        CP_COMMIT();
    };

    issue(0, 0); issue(1, 1); issue(2, 2);
    #pragma unroll 1
    for (int c = 0; c < 8; c++) {
        if (c <= 5)      { CP_WAIT(2); }
        else if (c == 6) { CP_WAIT(1); }
        else             { CP_WAIT(0); }
        __syncthreads();
        int buf = c % 3;
        uint32_t st = sbase + buf * STAGE;
        uint32_t sAhi = st, sAlo = st + 9216, sWhi = st + 18432, sWlo = st + 27648;
        #pragma unroll
        for (int kf = 0; kf < 4; kf++) {
            uint32_t ah[4], al[4], bh0[4], bh1[4], bl0[4], bl1[4];
            ldsm4(ah,  sAhi + aoff + kf * 32);
            ldsm4(al,  sAlo + aoff + kf * 32);
            ldsm4(bh0, sWhi + boff + kf * 32);
            ldsm4(bh1, sWhi + boff + 2304 + kf * 32);
            ldsm4(bl0, sWlo + boff + kf * 32);
            ldsm4(bl1, sWlo + boff + 2304 + kf * 32);
            mma16816(acc[0], ah, bh0); mma16816(acc[1], ah, bh0 + 2);
            mma16816(acc[2], ah, bh1); mma16816(acc[3], ah, bh1 + 2);
            mma16816(acc[0], ah, bl0); mma16816(acc[1], ah, bl0 + 2);
            mma16816(acc[2], ah, bl1); mma16816(acc[3], ah, bl1 + 2);
            mma16816(acc[0], al, bh0); mma16816(acc[1], al, bh0 + 2);
            mma16816(acc[2], al, bh1); mma16816(acc[3], al, bh1 + 2);
        }
        __syncthreads();
        if (c + 3 < 8) issue(c + 3, buf);
    }

    // ---- epilogue: gates, c/h update, next-step A image ----
    int j0 = ntile * 16 + wc * 8 + (lane & 3) * 2;
    float bi[4][2];
    #pragma unroll
    for (int g = 0; g < 4; g++) { bi[g][0] = bias[g * DM + j0]; bi[g][1] = bias[g * DM + j0 + 1]; }

    const int chunkA = ntile >> 2;
    unsigned char* imgHi = g_Hbf + ((size_t)(((par ^ 1) * 8 + chunkA) * 2)) * AIMG;
    unsigned char* imgLo = imgHi + AIMG;
    size_t colOff = (size_t)((ntile & 3) * 16 + wc * 8 + (lane & 3) * 2) * 2;

    #pragma unroll
    for (int rowi = 0; rowi < 2; rowi++) {
        int b = mq * 64 + wr * 16 + (lane >> 2) + rowi * 8;
        float h2[2];
        #pragma unroll
        for (int cp = 0; cp < 2; cp++) {
            int j = j0 + cp;
            float gi = acc[0][rowi * 2 + cp] + bi[0][cp];
            float gf = acc[1][rowi * 2 + cp] + bi[1][cp];
            float gg = acc[2][rowi * 2 + cp] + bi[2][cp];
            float go = acc[3][rowi * 2 + cp] + bi[3][cp];
            if (pre) {
                const float* pb = pre + (size_t)b * (TSEQ * G4);
                gi += pb[j]; gf += pb[DM + j]; gg += pb[2 * DM + j]; go += pb[3 * DM + j];
            }
            size_t ci = (size_t)b * DM + j;
            float cn = sigf(gf) * g_c[ci] + sigf(gi) * tanhf(gg);
            float hn = sigf(go) * tanhf(cn);
            g_c[ci] = cn;
            if (hstore) hstore[ci] = hn;
            h2[cp] = hn;
        }
        uint32_t hw, lw;
        bfsplit2(h2[0], h2[1], hw, lw);
        size_t off = (size_t)b * 144 + colOff;
        *(uint32_t*)(imgHi + off) = hw;
        *(uint32_t*)(imgLo + off) = lw;
    }
}

// ---------------- out: Y = Hdec @ Wp^T + bp, denormalize -----------------------
__global__ __launch_bounds__(256) void out_kernel(const float* __restrict__ Wp,
                                                  const float* __restrict__ bp,
                                                  float* __restrict__ out) {
    __shared__ float As[64 * 17];
    __shared__ float Bs[16 * 66];
    int tid = threadIdx.x;
    int n0 = blockIdx.x * 64;
    int m0 = blockIdx.y * 64;
    int tr = tid >> 4, tc = tid & 15;
    unsigned long long acc[4][2] = {};
    for (int k0 = 0; k0 < DM; k0 += 16) {
        #pragma unroll
        for (int i = 0; i < 4; i++) {
            int l = tid + 256 * i;
            int mr = l >> 4, kk = l & 15;
            As[mr * 17 + kk] = g_Hdec[(size_t)(m0 + mr) * DM + k0 + kk];
        }
        #pragma unroll
        for (int i = 0; i < 4; i++) {
            int l = tid + 256 * i;
            int nr = l >> 4, kk = l & 15;
            int n = n0 + nr;
            Bs[kk * 66 + nr] = (n < CIN) ? Wp[(size_t)n * DM + k0 + kk] : 0.f;
        }
        __syncthreads();
        #pragma unroll
        for (int kk = 0; kk < 16; kk++) {
            unsigned long long a[4];
            #pragma unroll
            for (int r = 0; r < 4; r++) a[r] = dup2(As[(tr * 4 + r) * 17 + kk]);
            const unsigned long long* wrow =
                reinterpret_cast<const unsigned long long*>(&Bs[kk * 66 + tc * 4]);
            unsigned long long w0 = wrow[0], w1 = wrow[1];
            #pragma unroll
            for (int r = 0; r < 4; r++) { fma2(acc[r][0], a[r], w0); fma2(acc[r][1], a[r], w1); }
        }
        __syncthreads();
    }
    #pragma unroll
    for (int r = 0; r < 4; r++) {
        int m = m0 + tr * 4 + r;
        int t = m >> 8, b = m & 255;
        float vals[4] = { lo32(acc[r][0]), hi32(acc[r][0]), lo32(acc[r][1]), hi32(acc[r][1]) };
        #pragma unroll
        for (int cc = 0; cc < 4; cc++) {
            int n = n0 + tc * 4 + cc;
            if (n < CIN) {
                int bc = b * CIN + n;
                out[(size_t)b * PRED * CIN + (size_t)t * CIN + n] =
                    (vals[cc] + bp[n]) * g_std[bc] + g_mean[bc];
            }
        }
    }
}

// ---------------- host launcher ------------------------------------------------
extern "C" void kernel_launch(void* const* d_in, const int* in_sizes, int n_in,
                              void* d_out, int out_size) {
    const float* x   = (const float*)d_in[0];
    const float* Wih = (const float*)d_in[1];
    const float* Whh = (const float*)d_in[2];
    const float* bih = (const float*)d_in[3];
    const float* bhh = (const float*)d_in[4];
    const float* Wp  = (const float*)d_in[5];
    const float* bp  = (const float*)d_in[6];
    float* out = (float*)d_out;

    float *gx, *wd, *bd, *benc, *hdec;
    unsigned char *wte, *wtd;
    cudaGetSymbolAddress((void**)&gx,   g_Gx);
    cudaGetSymbolAddress((void**)&wd,   g_Wd);
    cudaGetSymbolAddress((void**)&bd,   g_bd);
    cudaGetSymbolAddress((void**)&benc, g_benc);
    cudaGetSymbolAddress((void**)&hdec, g_Hdec);
    cudaGetSymbolAddress((void**)&wte,  g_WTe);
    cudaGetSymbolAddress((void**)&wtd,  g_WTd);

    cudaFuncSetAttribute(step_kernel, cudaFuncAttributeMaxDynamicSharedMemorySize, STEP_SMEM);
    cudaFuncSetAttribute(gxmma_kernel, cudaFuncAttributeMaxDynamicSharedMemorySize, GX_SMEM);

    stats_kernel<<<(BATCH * CIN + 255) / 256, 256>>>(x);
    bias_kernel<<<(G4 + 255) / 256, 256>>>(bih, bhh, Wih, bp);
    wd_kernel<<<dim3(DM / 64, G4 / 64), 256>>>(Wih, Wp, Whh);
    xsplit_kernel<<<(BATCH * TSEQ * CIN + 255) / 256, 256>>>(x);
    wihsplit_kernel<<<dim3(6, 32), 256>>>(Wih);
    wsplit_kernel<<<dim3(8, 32), 256>>>(Whh, wte);
    wsplit_kernel<<<dim3(8, 32), 256>>>(wd, wtd);
    init_kernel<<<((int)(sizeof(g_Hbf) / 4) + 255) / 256, 256>>>();
    gxmma_kernel<<<dim3(32, 192), 256, GX_SMEM>>>();

    for (int s = 0; s < TSEQ + PRED - 1; s++) {
        bool enc = (s < TSEQ);
        int par = s & 1;
        const unsigned char* Wt = enc ? wte : wtd;
        const float* pre  = enc ? (gx + (size_t)s * G4) : nullptr;
        const float* bias = enc ? benc : bd;
        float* hst = (s >= TSEQ - 1) ? (hdec + (size_t)(s - (TSEQ - 1)) * HD) : nullptr;
        step_kernel<<<dim3(32, 4), 256, STEP_SMEM>>>(par, Wt, pre, bias, hst);
    }

    out_kernel<<<dim3(6, (PRED * BATCH) / 64), 256>>>(Wp, bp, out);
    (void)in_sizes; (void)n_in; (void)out_size;
}

// round 6
// speedup vs baseline: 3.0158x; 1.1848x over previous
#include <cuda_runtime.h>
#include <cuda_bf16.h>
#include <math.h>
#include <stdint.h>

#define BATCH 256
#define TSEQ  96
#define PRED  96
#define CIN   321
#define DM    512
#define G4    2048
#define HD    (BATCH*DM)
#define NSTEP (TSEQ+PRED-1)     // 191

#define AIMG  36864u            // 256 rows x 144 B per (chunk,split)
#define WIMG  9216u             // 64 rows x 144 B per (chunk,split)
#define XIMG  (24576u*144u)

// ---------------- device scratch ----------------------------------------------
__device__ float g_mean[BATCH*CIN];
__device__ float g_std [BATCH*CIN];
__device__ float g_istd[BATCH*CIN];
__device__ float g_Gx  [(size_t)BATCH*TSEQ*G4];
__device__ float g_Wd  [G4*DM];
__device__ float g_bd  [G4];
__device__ float g_benc[G4];
__device__ float g_Hdec[(size_t)PRED*HD];
__device__ unsigned g_bar[NSTEP+1];
// bf16 hidden images: [par2][chunk8][split2][256][72]
__device__ __align__(1024) unsigned char g_Hbf[2*8*2*AIMG];
// recurrent W images: [ntile32][chunk8][split2][64][72]
__device__ __align__(1024) unsigned char g_WTe[32*8*2*WIMG];
__device__ __align__(1024) unsigned char g_WTd[32*8*2*WIMG];
// gx operand images
__device__ __align__(1024) unsigned char g_Xbf[6*2*XIMG];
__device__ __align__(1024) unsigned char g_WIe[32*6*2*WIMG];

// ---------------- helpers ------------------------------------------------------
__device__ __forceinline__ float sigf(float x) { return 1.f / (1.f + expf(-x)); }

__device__ __forceinline__ unsigned long long dup2(float x) {
    unsigned long long r;
    asm("mov.b64 %0, {%1, %2};" : "=l"(r) : "f"(x), "f"(x));
    return r;
}
__device__ __forceinline__ void fma2(unsigned long long& d, unsigned long long a, unsigned long long b) {
    asm("fma.rn.f32x2 %0, %1, %2, %0;" : "+l"(d) : "l"(a), "l"(b));
}
__device__ __forceinline__ float lo32(unsigned long long v) { return __uint_as_float((unsigned)v); }
__device__ __forceinline__ float hi32(unsigned long long v) { return __uint_as_float((unsigned)(v >> 32)); }

__device__ __forceinline__ uint32_t smem_u32(const void* p) {
    uint32_t a;
    asm("{ .reg .u64 t; cvta.to.shared.u64 t, %1; cvt.u32.u64 %0, t; }" : "=r"(a) : "l"(p));
    return a;
}
__device__ __forceinline__ void cpasync16(uint32_t dst, const void* src) {
    asm volatile("cp.async.cg.shared.global [%0], [%1], 16;" :: "r"(dst), "l"(src) : "memory");
}
#define CP_COMMIT() asm volatile("cp.async.commit_group;" ::: "memory")
#define CP_WAIT(N)  asm volatile("cp.async.wait_group %0;" :: "n"(N) : "memory")

__device__ __forceinline__ void ldsm4(uint32_t* r, uint32_t addr) {
    asm volatile("ldmatrix.sync.aligned.m8n8.x4.shared.b16 {%0,%1,%2,%3}, [%4];"
        : "=r"(r[0]), "=r"(r[1]), "=r"(r[2]), "=r"(r[3]) : "r"(addr));
}
__device__ __forceinline__ void mma16816(float* d, const uint32_t* a, const uint32_t* b) {
    asm volatile("mma.sync.aligned.m16n8k16.row.col.f32.bf16.bf16.f32 "
        "{%0,%1,%2,%3}, {%4,%5,%6,%7}, {%8,%9}, {%0,%1,%2,%3};"
        : "+f"(d[0]), "+f"(d[1]), "+f"(d[2]), "+f"(d[3])
        : "r"(a[0]), "r"(a[1]), "r"(a[2]), "r"(a[3]), "r"(b[0]), "r"(b[1]));
}
__device__ __forceinline__ void bfsplit2(float a, float b, uint32_t& hw, uint32_t& lw) {
    __nv_bfloat16 h0 = __float2bfloat16(a), h1 = __float2bfloat16(b);
    float r0 = a - __bfloat162float(h0), r1 = b - __bfloat162float(h1);
    __nv_bfloat16 l0 = __float2bfloat16(r0), l1 = __float2bfloat16(r1);
    hw = (uint32_t)__bfloat16_as_ushort(h0) | ((uint32_t)__bfloat16_as_ushort(h1) << 16);
    lw = (uint32_t)__bfloat16_as_ushort(l0) | ((uint32_t)__bfloat16_as_ushort(l1) << 16);
}

// ---------------- stats --------------------------------------------------------
__global__ __launch_bounds__(256) void stats_kernel(const float* __restrict__ x) {
    int idx = blockIdx.x * 256 + threadIdx.x;
    if (idx >= BATCH * CIN) return;
    int b = idx / CIN, ch = idx % CIN;
    float s = 0.f, ss = 0.f;
    const float* p = x + (size_t)b * TSEQ * CIN + ch;
    #pragma unroll 4
    for (int t = 0; t < TSEQ; t++) { float v = p[t * CIN]; s += v; ss += v * v; }
    float mean = s * (1.f / TSEQ);
    float var = ss * (1.f / TSEQ) - mean * mean;
    if (var < 0.f) var = 0.f;
    float sd = sqrtf(var + 1e-5f);
    g_mean[idx] = mean; g_std[idx] = sd; g_istd[idx] = 1.f / sd;
}

// ---------------- bias fold ----------------------------------------------------
__global__ __launch_bounds__(256) void bias_kernel(const float* __restrict__ bih,
                                                   const float* __restrict__ bhh,
                                                   const float* __restrict__ Wih,
                                                   const float* __restrict__ bp) {
    int n = blockIdx.x * 256 + threadIdx.x;
    if (n >= G4) return;
    float be = bih[n] + bhh[n];
    float s = 0.f;
    const float* w = Wih + (size_t)n * CIN;
    for (int j = 0; j < CIN; j++) s += w[j] * bp[j];
    g_benc[n] = be;
    g_bd[n] = be + s;
}

// ---------------- Wd = Whh + Wih @ Wp ------------------------------------------
__global__ __launch_bounds__(256) void wd_kernel(const float* __restrict__ Wih,
                                                 const float* __restrict__ Wp,
                                                 const float* __restrict__ Whh) {
    __shared__ float As[64 * 17];
    __shared__ float Bs[16 * 65];
    int tid = threadIdx.x;
    int n0 = blockIdx.x * 64;
    int m0 = blockIdx.y * 64;
    int tr = tid >> 4, tc = tid & 15;
    float acc[4][4] = {};
    for (int j0 = 0; j0 < CIN; j0 += 16) {
        #pragma unroll
        for (int i = 0; i < 4; i++) {
            int l = tid + 256 * i;
            int mr = l >> 4, jj = l & 15;
            int j = j0 + jj;
            As[mr * 17 + jj] = (j < CIN) ? Wih[(size_t)(m0 + mr) * CIN + j] : 0.f;
        }
        #pragma unroll
        for (int i = 0; i < 4; i++) {
            int l = tid + 256 * i;
            int jj = l >> 6, nr = l & 63;
            int j = j0 + jj;
            Bs[jj * 65 + nr] = (j < CIN) ? Wp[(size_t)j * DM + n0 + nr] : 0.f;
        }
        __syncthreads();
        #pragma unroll
        for (int jj = 0; jj < 16; jj++) {
            float a[4], bb[4];
            #pragma unroll
            for (int r = 0; r < 4; r++) a[r] = As[(tr * 4 + r) * 17 + jj];
            #pragma unroll
            for (int cc = 0; cc < 4; cc++) bb[cc] = Bs[jj * 65 + tc * 4 + cc];
            #pragma unroll
            for (int r = 0; r < 4; r++)
                #pragma unroll
                for (int cc = 0; cc < 4; cc++) acc[r][cc] += a[r] * bb[cc];
        }
        __syncthreads();
    }
    #pragma unroll
    for (int r = 0; r < 4; r++) {
        int m = m0 + tr * 4 + r;
        #pragma unroll
        for (int cc = 0; cc < 4; cc++) {
            int n = n0 + tc * 4 + cc;
            g_Wd[(size_t)m * DM + n] = Whh[(size_t)m * DM + n] + acc[r][cc];
        }
    }
}

// ---------------- recurrent W image builder ------------------------------------
__global__ __launch_bounds__(256) void wsplit_kernel(const float* __restrict__ src,
                                                     unsigned char* __restrict__ dst) {
    int chunk = blockIdx.x;
    int ntile = blockIdx.y;
    int tid = threadIdx.x;
    int rr = tid >> 2;
    int q  = tid & 3;
    int joct = rr >> 5, rem = rr & 31;
    int gate = rem >> 3, j7 = rem & 7;
    int srow = gate * DM + ntile * 16 + joct * 8 + j7;
    unsigned char* d0 = dst + ((size_t)(ntile * 8 + chunk) * 2) * WIMG;
    #pragma unroll
    for (int c = 0; c < 18; c++) {
        int col = q * 18 + c;
        float v = (col < 64) ? src[(size_t)srow * DM + chunk * 64 + col] : 0.f;
        __nv_bfloat16 hb = __float2bfloat16(v);
        float rem2 = v - __bfloat162float(hb);
        __nv_bfloat16 lb = __float2bfloat16(rem2);
        size_t off = (size_t)rr * 144 + col * 2;
        *(__nv_bfloat16*)(d0 + off)        = hb;
        *(__nv_bfloat16*)(d0 + WIMG + off) = lb;
    }
}

// ---------------- Wih image builder for gx -------------------------------------
__global__ __launch_bounds__(256) void wihsplit_kernel(const float* __restrict__ Wih) {
    int chunk = blockIdx.x;
    int ntile = blockIdx.y;
    int tid = threadIdx.x;
    int rr = tid >> 2;
    int q  = tid & 3;
    int srow = ntile * 64 + rr;
    unsigned char* d0 = g_WIe + ((size_t)(ntile * 6 + chunk) * 2) * WIMG;
    #pragma unroll
    for (int c = 0; c < 18; c++) {
        int col = q * 18 + c;
        int k = chunk * 64 + col;
        float v = (col < 64 && k < CIN) ? Wih[(size_t)srow * CIN + k] : 0.f;
        __nv_bfloat16 hb = __float2bfloat16(v);
        float rem2 = v - __bfloat162float(hb);
        __nv_bfloat16 lb = __float2bfloat16(rem2);
        size_t off = (size_t)rr * 144 + col * 2;
        *(__nv_bfloat16*)(d0 + off)        = hb;
        *(__nv_bfloat16*)(d0 + WIMG + off) = lb;
    }
}

// ---------------- x normalize+split images -------------------------------------
__global__ __launch_bounds__(256) void xsplit_kernel(const float* __restrict__ x) {
    int idx = blockIdx.x * 256 + threadIdx.x;
    if (idx >= BATCH * TSEQ * CIN) return;
    int m = idx / CIN, k = idx - m * CIN;
    int b = m / TSEQ;
    int bc = b * CIN + k;
    float v = (x[idx] - g_mean[bc]) * g_istd[bc];
    __nv_bfloat16 hb = __float2bfloat16(v);
    float rem = v - __bfloat162float(hb);
    __nv_bfloat16 lb = __float2bfloat16(rem);
    int chunk = k >> 6, col = k & 63;
    size_t offh = ((size_t)(chunk * 2) * 24576 + m) * 144 + col * 2;
    *(__nv_bfloat16*)(g_Xbf + offh)        = hb;
    *(__nv_bfloat16*)(g_Xbf + offh + XIMG) = lb;
}

// ---------------- init ----------------------------------------------------------
__global__ __launch_bounds__(256) void init_kernel() {
    int i = blockIdx.x * 256 + threadIdx.x;
    if (i < (int)(sizeof(g_Hbf) / 4)) ((uint32_t*)g_Hbf)[i] = 0u;
    if (i <= NSTEP) g_bar[i] = 0u;
}

// ---------------- gx = xnorm @ Wih^T via HMMA split ----------------------------
#define GXSTAGE 55296
#define GX_SMEM (2*GXSTAGE)
__global__ void __launch_bounds__(256, 1) gxmma_kernel() {
    extern __shared__ unsigned char smem[];
    const int tid = threadIdx.x;
    const int w = tid >> 5, lane = tid & 31;
    const int n0 = blockIdx.x * 64;
    const int m0 = blockIdx.y * 128;
    uint32_t sbase = smem_u32(smem);
    float acc[8][4];
    #pragma unroll
    for (int f = 0; f < 8; f++)
        #pragma unroll
        for (int r = 0; r < 4; r++) acc[f][r] = 0.f;

    const uint32_t aoff = (uint32_t)((w * 16 + (lane & 15)) * 144 + (lane >> 4) * 16);
    const uint32_t boff = (uint32_t)(((((lane >> 4) & 1) * 8) + (lane & 7)) * 144 + ((lane >> 3) & 1) * 16);
    const unsigned char* Bbase = g_WIe + ((size_t)blockIdx.x * 6 * 2) * WIMG;

    auto issue = [&](int chunk, int buf) {
        uint32_t sb = sbase + buf * GXSTAGE;
        #pragma unroll
        for (int i = 0; i < 14; i++) {
            int idx = tid + i * 256;
            if (idx >= 3456) break;
            uint32_t dst; const unsigned char* src;
            if (idx < 2304) {
                int sp = idx / 1152; int off = (idx - sp * 1152) * 16;
                dst = sb + sp * 18432 + off;
                src = g_Xbf + (size_t)(chunk * 2 + sp) * XIMG + (size_t)m0 * 144 + off;
            } else {
                int j = idx - 2304; int sp = j / 576; int off = (j - sp * 576) * 16;
                dst = sb + 36864 + sp * 9216 + off;
                src = Bbase + (size_t)(chunk * 2 + sp) * WIMG + off;
            }
            cpasync16(dst, src);
        }
        CP_COMMIT();
    };

    issue(0, 0); issue(1, 1);
    #pragma unroll 1
    for (int c = 0; c < 6; c++) {
        if (c < 5) { CP_WAIT(1); } else { CP_WAIT(0); }
        __syncthreads();
        uint32_t st = sbase + (c & 1) * GXSTAGE;
        uint32_t sAhi = st, sAlo = st + 18432, sWhi = st + 36864, sWlo = st + 46080;
        #pragma unroll
        for (int kf = 0; kf < 4; kf++) {
            uint32_t ah[4], al[4], bh[4][4], bl[4][4];
            ldsm4(ah, sAhi + aoff + kf * 32);
            ldsm4(al, sAlo + aoff + kf * 32);
            #pragma unroll
            for (int ng = 0; ng < 4; ng++) {
                ldsm4(bh[ng], sWhi + boff + ng * 2304 + kf * 32);
                ldsm4(bl[ng], sWlo + boff + ng * 2304 + kf * 32);
            }
            #pragma unroll
            for (int ng = 0; ng < 4; ng++) { mma16816(acc[2*ng], ah, bh[ng]); mma16816(acc[2*ng+1], ah, bh[ng]+2); }
            #pragma unroll
            for (int ng = 0; ng < 4; ng++) { mma16816(acc[2*ng], ah, bl[ng]); mma16816(acc[2*ng+1], ah, bl[ng]+2); }
            #pragma unroll
            for (int ng = 0; ng < 4; ng++) { mma16816(acc[2*ng], al, bh[ng]); mma16816(acc[2*ng+1], al, bh[ng]+2); }
        }
        __syncthreads();
        if (c + 2 < 6) issue(c + 2, c & 1);
    }
    #pragma unroll
    for (int f = 0; f < 8; f++) {
        int n = n0 + (f >> 1) * 16 + (f & 1) * 8 + (lane & 3) * 2;
        #pragma unroll
        for (int rowi = 0; rowi < 2; rowi++) {
            int m = m0 + w * 16 + (lane >> 2) + rowi * 8;
            *(float2*)&g_Gx[(size_t)m * G4 + n] = make_float2(acc[f][rowi*2], acc[f][rowi*2+1]);
        }
    }
}

// ---------------- persistent LSTM kernel ----------------------------------------
// grid (32 ntile, 4 mq), 256 thr. W phase-resident in smem; c in registers.
// smem: Wcache[16*9216=147456] | Abuf[3*18432=55296]  -> 202752 B
#define WCACHE_B 147456
#define ABUF_B   18432
#define PERSIST_SMEM (WCACHE_B + 3*ABUF_B)

__global__ void __launch_bounds__(256, 1) persist_kernel(const float* __restrict__ gx,
                                                         const float* __restrict__ benc,
                                                         const float* __restrict__ bd,
                                                         float* __restrict__ hdec) {
    extern __shared__ unsigned char smem[];
    const int tid = threadIdx.x;
    const int w = tid >> 5, lane = tid & 31;
    const int wr = w & 3, wc = w >> 2;
    const int ntile = blockIdx.x, mq = blockIdx.y;
    uint32_t sbase = smem_u32(smem);
    uint32_t Wc = sbase;
    uint32_t Ab = sbase + WCACHE_B;

    const uint32_t aoff = (uint32_t)((wr * 16 + (lane & 15)) * 144 + (lane >> 4) * 16);
    const uint32_t boff = (uint32_t)((wc * 32 + ((lane >> 4) & 1) * 8 + (lane & 7)) * 144 + ((lane >> 3) & 1) * 16);

    const unsigned char* WEsrc = g_WTe + ((size_t)(ntile * 8) * 2) * WIMG;
    const unsigned char* WDsrc = g_WTd + ((size_t)(ntile * 8) * 2) * WIMG;

    auto loadW = [&](const unsigned char* src) {
        #pragma unroll 4
        for (int i = 0; i < 36; i++) {
            int idx = tid + i * 256;                 // 0..9215
            int img = idx / 576;
            int off = (idx - img * 576) * 16;
            cpasync16(Wc + img * 9216 + off, src + (size_t)img * WIMG + off);
        }
        CP_COMMIT();
    };
    auto loadA = [&](const unsigned char* Apar, int chunk, int buf) {
        #pragma unroll
        for (int i = 0; i < 5; i++) {
            int idx = tid + i * 256;
            if (idx < 1152) {
                int split = idx / 576;
                int off = (idx - split * 576) * 16;
                cpasync16(Ab + buf * ABUF_B + split * 9216 + off,
                          Apar + (size_t)(chunk * 2 + split) * AIMG + mq * 9216 + off);
            }
        }
        CP_COMMIT();
    };

    // thread cell coordinates
    const int j0 = ntile * 16 + wc * 8 + (lane & 3) * 2;
    const int bbase = mq * 64 + wr * 16 + (lane >> 2);
    const int chunkA = ntile >> 2;
    const size_t colOff = (size_t)((ntile & 3) * 16 + wc * 8 + (lane & 3) * 2) * 2;

    float bi[4][2];
    #pragma unroll
    for (int g = 0; g < 4; g++) { bi[g][0] = benc[g * DM + j0]; bi[g][1] = benc[g * DM + j0 + 1]; }
    float creg[4] = {0.f, 0.f, 0.f, 0.f};

    loadW(WEsrc);
    CP_WAIT(0);
    __syncthreads();

    for (int s = 0; s < NSTEP; s++) {
        const bool enc = (s < TSEQ);
        if (s == TSEQ) {
            __syncthreads();
            loadW(WDsrc);
            #pragma unroll
            for (int g = 0; g < 4; g++) { bi[g][0] = bd[g * DM + j0]; bi[g][1] = bd[g * DM + j0 + 1]; }
            CP_WAIT(0);
            __syncthreads();
        }
        const int par = s & 1;
        const unsigned char* Apar = g_Hbf + (size_t)(par * 16) * AIMG;

        // prefetch encoder pre-activations into registers (latency hidden by MMA loop)
        float pr[16];
        if (enc) {
            #pragma unroll
            for (int rowi = 0; rowi < 2; rowi++) {
                const float* gr = gx + ((size_t)(bbase + rowi * 8) * TSEQ + s) * G4;
                #pragma unroll
                for (int g = 0; g < 4; g++) {
                    float2 v = *(const float2*)&gr[g * DM + j0];
                    pr[rowi * 8 + g * 2]     = v.x;
                    pr[rowi * 8 + g * 2 + 1] = v.y;
                }
            }
        }

        float acc[4][4];
        #pragma unroll
        for (int g = 0; g < 4; g++)
            #pragma unroll
            for (int r = 0; r < 4; r++) acc[g][r] = 0.f;

        loadA(Apar, 0, 0);
        loadA(Apar, 1, 1);
        #pragma unroll 1
        for (int c = 0; c < 8; c++) {
            if (c + 2 < 8) { loadA(Apar, c + 2, (c + 2) % 3); CP_WAIT(2); }
            else if (c == 6) { CP_WAIT(1); }
            else if (c == 7) { CP_WAIT(0); }
            __syncthreads();
            uint32_t at = Ab + (c % 3) * ABUF_B;
            uint32_t sAhi = at, sAlo = at + 9216;
            uint32_t wt = Wc + c * 18432;
            uint32_t sWhi = wt, sWlo = wt + 9216;
            #pragma unroll
            for (int kf = 0; kf < 4; kf++) {
                uint32_t ah[4], al[4], bh0[4], bh1[4], bl0[4], bl1[4];
                ldsm4(ah,  sAhi + aoff + kf * 32);
                ldsm4(al,  sAlo + aoff + kf * 32);
                ldsm4(bh0, sWhi + boff + kf * 32);
                ldsm4(bh1, sWhi + boff + 2304 + kf * 32);
                ldsm4(bl0, sWlo + boff + kf * 32);
                ldsm4(bl1, sWlo + boff + 2304 + kf * 32);
                mma16816(acc[0], ah, bh0); mma16816(acc[1], ah, bh0 + 2);
                mma16816(acc[2], ah, bh1); mma16816(acc[3], ah, bh1 + 2);
                mma16816(acc[0], ah, bl0); mma16816(acc[1], ah, bl0 + 2);
                mma16816(acc[2], ah, bl1); mma16816(acc[3], ah, bl1 + 2);
                mma16816(acc[0], al, bh0); mma16816(acc[1], al, bh0 + 2);
                mma16816(acc[2], al, bh1); mma16816(acc[3], al, bh1 + 2);
            }
            __syncthreads();
        }

        // ---- epilogue ----
        unsigned char* imgHi = g_Hbf + (size_t)(((par ^ 1) * 8 + chunkA) * 2) * AIMG;
        unsigned char* imgLo = imgHi + AIMG;
        float* hst = (s >= TSEQ - 1) ? (hdec + (size_t)(s - (TSEQ - 1)) * HD) : nullptr;

        #pragma unroll
        for (int rowi = 0; rowi < 2; rowi++) {
            int b = bbase + rowi * 8;
            float h2[2];
            #pragma unroll
            for (int cp = 0; cp < 2; cp++) {
                float gi = acc[0][rowi * 2 + cp] + bi[0][cp];
                float gf = acc[1][rowi * 2 + cp] + bi[1][cp];
                float gg = acc[2][rowi * 2 + cp] + bi[2][cp];
                float go = acc[3][rowi * 2 + cp] + bi[3][cp];
                if (enc) {
                    gi += pr[rowi * 8 + 0 + cp];
                    gf += pr[rowi * 8 + 2 + cp];
                    gg += pr[rowi * 8 + 4 + cp];
                    go += pr[rowi * 8 + 6 + cp];
                }
                float cn = sigf(gf) * creg[rowi * 2 + cp] + sigf(gi) * tanhf(gg);
                float hn = sigf(go) * tanhf(cn);
                creg[rowi * 2 + cp] = cn;
                if (hst) hst[(size_t)b * DM + j0 + cp] = hn;
                h2[cp] = hn;
            }
            uint32_t hw, lw;
            bfsplit2(h2[0], h2[1], hw, lw);
            size_t off = (size_t)b * 144 + colOff;
            *(uint32_t*)(imgHi + off) = hw;
            *(uint32_t*)(imgLo + off) = lw;
        }

        // ---- grid barrier ----
        if (s < NSTEP - 1) {
            __threadfence();
            __syncthreads();
            if (tid == 0) {
                unsigned prev = atomicAdd(&g_bar[s], 1u);
                if (prev != 127u) {
                    unsigned v;
                    unsigned* p = &g_bar[s];
                    do {
                        asm volatile("ld.acquire.gpu.u32 %0, [%1];" : "=r"(v) : "l"(p) : "memory");
                    } while (v < 128u);
                }
            }
            __syncthreads();
        }
    }
}

// ---------------- out: Y = Hdec @ Wp^T + bp, denormalize -----------------------
__global__ __launch_bounds__(256) void out_kernel(const float* __restrict__ Wp,
                                                  const float* __restrict__ bp,
                                                  float* __restrict__ out) {
    __shared__ float As[64 * 17];
    __shared__ float Bs[16 * 66];
    int tid = threadIdx.x;
    int n0 = blockIdx.x * 64;
    int m0 = blockIdx.y * 64;
    int tr = tid >> 4, tc = tid & 15;
    unsigned long long acc[4][2] = {};
    for (int k0 = 0; k0 < DM; k0 += 16) {
        #pragma unroll
        for (int i = 0; i < 4; i++) {
            int l = tid + 256 * i;
            int mr = l >> 4, kk = l & 15;
            As[mr * 17 + kk] = g_Hdec[(size_t)(m0 + mr) * DM + k0 + kk];
        }
        #pragma unroll
        for (int i = 0; i < 4; i++) {
            int l = tid + 256 * i;
            int nr = l >> 4, kk = l & 15;
            int n = n0 + nr;
            Bs[kk * 66 + nr] = (n < CIN) ? Wp[(size_t)n * DM + k0 + kk] : 0.f;
        }
        __syncthreads();
        #pragma unroll
        for (int kk = 0; kk < 16; kk++) {
            unsigned long long a[4];
            #pragma unroll
            for (int r = 0; r < 4; r++) a[r] = dup2(As[(tr * 4 + r) * 17 + kk]);
            const unsigned long long* wrow =
                reinterpret_cast<const unsigned long long*>(&Bs[kk * 66 + tc * 4]);
            unsigned long long w0 = wrow[0], w1 = wrow[1];
            #pragma unroll
            for (int r = 0; r < 4; r++) { fma2(acc[r][0], a[r], w0); fma2(acc[r][1], a[r], w1); }
        }
        __syncthreads();
    }
    #pragma unroll
    for (int r = 0; r < 4; r++) {
        int m = m0 + tr * 4 + r;
        int t = m >> 8, b = m & 255;
        float vals[4] = { lo32(acc[r][0]), hi32(acc[r][0]), lo32(acc[r][1]), hi32(acc[r][1]) };
        #pragma unroll
        for (int cc = 0; cc < 4; cc++) {
            int n = n0 + tc * 4 + cc;
            if (n < CIN) {
                int bc = b * CIN + n;
                out[(size_t)b * PRED * CIN + (size_t)t * CIN + n] =
                    (vals[cc] + bp[n]) * g_std[bc] + g_mean[bc];
            }
        }
    }
}

// ---------------- host launcher ------------------------------------------------
extern "C" void kernel_launch(void* const* d_in, const int* in_sizes, int n_in,
                              void* d_out, int out_size) {
    const float* x   = (const float*)d_in[0];
    const float* Wih = (const float*)d_in[1];
    const float* Whh = (const float*)d_in[2];
    const float* bih = (const float*)d_in[3];
    const float* bhh = (const float*)d_in[4];
    const float* Wp  = (const float*)d_in[5];
    const float* bp  = (const float*)d_in[6];
    float* out = (float*)d_out;

    float *gx, *wd, *bd, *benc, *hdec;
    unsigned char *wte, *wtd;
    cudaGetSymbolAddress((void**)&gx,   g_Gx);
    cudaGetSymbolAddress((void**)&wd,   g_Wd);
    cudaGetSymbolAddress((void**)&bd,   g_bd);
    cudaGetSymbolAddress((void**)&benc, g_benc);
    cudaGetSymbolAddress((void**)&hdec, g_Hdec);
    cudaGetSymbolAddress((void**)&wte,  g_WTe);
    cudaGetSymbolAddress((void**)&wtd,  g_WTd);

    cudaFuncSetAttribute(persist_kernel, cudaFuncAttributeMaxDynamicSharedMemorySize, PERSIST_SMEM);
    cudaFuncSetAttribute(gxmma_kernel, cudaFuncAttributeMaxDynamicSharedMemorySize, GX_SMEM);

    stats_kernel<<<(BATCH * CIN + 255) / 256, 256>>>(x);
    bias_kernel<<<(G4 + 255) / 256, 256>>>(bih, bhh, Wih, bp);
    wd_kernel<<<dim3(DM / 64, G4 / 64), 256>>>(Wih, Wp, Whh);
    xsplit_kernel<<<(BATCH * TSEQ * CIN + 255) / 256, 256>>>(x);
    wihsplit_kernel<<<dim3(6, 32), 256>>>(Wih);
    wsplit_kernel<<<dim3(8, 32), 256>>>(Whh, wte);
    wsplit_kernel<<<dim3(8, 32), 256>>>(wd, wtd);
    init_kernel<<<((int)(sizeof(g_Hbf) / 4) + 255) / 256, 256>>>();
    gxmma_kernel<<<dim3(32, 192), 256, GX_SMEM>>>();

    persist_kernel<<<dim3(32, 4), 256, PERSIST_SMEM>>>(gx, benc, bd, hdec);

    out_kernel<<<dim3(6, (PRED * BATCH) / 64), 256>>>(Wp, bp, out);
    (void)in_sizes; (void)n_in; (void)out_size;
}